// round 5
// baseline (speedup 1.0000x reference)
#include <cuda_runtime.h>
#include <cuda_bf16.h>

#define NB 64      // batch
#define NL 512     // sequence length
#define ND 300     // embed dim
#define ND4 75     // float4 lanes per row
#define NC 128     // channels
#define CH 16      // token chunks per batch
#define TPC 32     // tokens per gather block (NL/CH)
#define WAYS 4
#define JPER 8     // tokens per way (TPC/WAYS)

// Scratch (__device__ globals per allocation rules)
__device__ float4 g_part4[NB * CH * 3 * ND4];  // partial g sums, f4

// ---------------------------------------------------------------------------
// Kernel 1: embedding gather + weighted partial reduction.
// grid = NB*CH = 1024 blocks, 320 threads = 80 f4 d-lanes x 4 token-ways.
// 6 blocks/SM resident -> ~60 warps to cover DRAM latency.
// ---------------------------------------------------------------------------
__global__ __launch_bounds__(320, 6) void gather_kernel(
    const int*   __restrict__ x,
    const float* __restrict__ embed_w,
    const float* __restrict__ fc3_w,
    const float* __restrict__ fc4_w,
    const float* __restrict__ fc5_w)
{
    const int b     = blockIdx.x >> 4;
    const int chunk = blockIdx.x & 15;

    __shared__ int    sidx[TPC];
    __shared__ float  sc[3][TPC];
    __shared__ float4 sred[WAYS][3][80];

    const int tid = threadIdx.x;
    const int d4  = tid % 80;
    const int y   = tid / 80;

    if (tid < TPC) {
        const int t = chunk * TPC + tid;
        sidx[tid] = x[b * NL + t];
        const float* wks[3] = {fc3_w, fc4_w, fc5_w};
        #pragma unroll
        for (int kk = 0; kk < 3; kk++) {
            const int k = kk + 3;
            int lo = t - k + 1; if (lo < 0) lo = 0;
            int hi = t; const int lim = NL - k - 1; if (hi > lim) hi = lim;
            float s = 0.f;
            for (int l = lo; l <= hi; l++) s += wks[kk][l];
            sc[kk][tid] = s;
        }
    }
    __syncthreads();

    float4 a0 = make_float4(0.f, 0.f, 0.f, 0.f);
    float4 a1 = a0, a2 = a0;

    if (d4 < ND4) {
        const float4* emb4 = (const float4*)embed_w;
        #pragma unroll 4
        for (int j = 0; j < JPER; j++) {
            const int jj = y * JPER + j;
            const float4 v = __ldg(&emb4[sidx[jj] * ND4 + d4]);
            const float c0 = sc[0][jj], c1 = sc[1][jj], c2 = sc[2][jj];
            a0.x = fmaf(c0, v.x, a0.x); a0.y = fmaf(c0, v.y, a0.y);
            a0.z = fmaf(c0, v.z, a0.z); a0.w = fmaf(c0, v.w, a0.w);
            a1.x = fmaf(c1, v.x, a1.x); a1.y = fmaf(c1, v.y, a1.y);
            a1.z = fmaf(c1, v.z, a1.z); a1.w = fmaf(c1, v.w, a1.w);
            a2.x = fmaf(c2, v.x, a2.x); a2.y = fmaf(c2, v.y, a2.y);
            a2.z = fmaf(c2, v.z, a2.z); a2.w = fmaf(c2, v.w, a2.w);
        }
    }
    sred[y][0][d4] = a0;
    sred[y][1][d4] = a1;
    sred[y][2][d4] = a2;
    __syncthreads();

    if (tid < 240) {
        const int kk = tid / 80;
        const int dd = tid % 80;
        if (dd < ND4) {
            float4 s = sred[0][kk][dd];
            #pragma unroll
            for (int w = 1; w < WAYS; w++) {
                const float4 v = sred[w][kk][dd];
                s.x += v.x; s.y += v.y; s.z += v.z; s.w += v.w;
            }
            g_part4[((b * CH + chunk) * 3 + kk) * ND4 + dd] = s;
        }
    }
}

// ---------------------------------------------------------------------------
// Kernel 2 (fused epilogue): reduce g_part -> g, conv -> h (smem), fc -> out.
// grid = 16 blocks (4 batches each), 512 threads = 128 channels x 4 batches.
// Dyn smem layout (float4 units):
//   W   [0 .. 12416)  : conv_w tile 128x75 (phase A), then fc_w 128x97 padded (phase C)
//   sg  [12416..13316): g[4][3*75]
//   sh  [13316..13700): h[4][96]
// Total 13700 f4 = 219200 B.
// ---------------------------------------------------------------------------
#define W_OFF   0
#define SG_OFF  12416
#define SH_OFF  13316
#define EPI_SMEM (13700 * 16)

__global__ __launch_bounds__(512, 1) void epilogue_kernel(
    const float* __restrict__ conv_w,
    const float* __restrict__ conv_b,
    const float* __restrict__ fc3_w,
    const float* __restrict__ fc3_b,
    const float* __restrict__ fc4_w,
    const float* __restrict__ fc4_b,
    const float* __restrict__ fc5_w,
    const float* __restrict__ fc5_b,
    const float* __restrict__ fc_w,
    const float* __restrict__ fc_b,
    float* __restrict__ out)
{
    extern __shared__ float4 dyn[];
    float4* W  = dyn + W_OFF;
    float4* sg = dyn + SG_OFF;
    float4* sh = dyn + SH_OFF;
    __shared__ float sSk[3];

    const int tid  = threadIdx.x;
    const int warp = tid >> 5;
    const int lane = tid & 31;
    const int b0   = blockIdx.x * 4;

    // S_k (warps 0-2)
    if (warp < 3) {
        const float* wks[3] = {fc3_w, fc4_w, fc5_w};
        const float* w = wks[warp];
        const int n = NL - (warp + 3);
        float s = 0.f;
        for (int l = lane; l < n; l += 32) s += w[l];
        #pragma unroll
        for (int off = 16; off > 0; off >>= 1)
            s += __shfl_xor_sync(0xFFFFFFFFu, s, off);
        if (lane == 0) sSk[warp] = s;
    }

    // Phase A1: stage full conv_w (128x75 f4), coalesced
    {
        const float4* cwg = (const float4*)conv_w;
        #pragma unroll
        for (int j = tid; j < NC * ND4; j += 512)
            W[j] = __ldg(&cwg[j]);
    }

    // Phase A2: reduce g_part chunks -> sg[bsub][225]
    for (int p = tid; p < 4 * 225; p += 512) {
        const int bsub = p / 225;
        const int pos  = p % 225;
        const float4* q = &g_part4[(b0 + bsub) * (CH * 225) + pos];
        float4 s = q[0];
        #pragma unroll
        for (int ch = 1; ch < CH; ch++) {
            const float4 v = q[ch * 225];
            s.x += v.x; s.y += v.y; s.z += v.z; s.w += v.w;
        }
        sg[bsub * 225 + pos] = s;
    }
    __syncthreads();

    // Phase B: private conv dots. thread -> (c = tid%128, bsub = tid/128)
    const int c    = tid & 127;
    const int bsub = tid >> 7;
    {
        float s0 = 0.f, s1 = 0.f, s2 = 0.f;
        #pragma unroll 5
        for (int i = 0; i < ND4; i++) {
            const float4 w  = W[c * ND4 + i];        // LDS.128, conflict-free phases
            const float4 g0 = sg[bsub * 225 + i];
            const float4 g1 = sg[bsub * 225 + 75 + i];
            const float4 g2 = sg[bsub * 225 + 150 + i];
            s0 = fmaf(w.x, g0.x, s0); s0 = fmaf(w.y, g0.y, s0);
            s0 = fmaf(w.z, g0.z, s0); s0 = fmaf(w.w, g0.w, s0);
            s1 = fmaf(w.x, g1.x, s1); s1 = fmaf(w.y, g1.y, s1);
            s1 = fmaf(w.z, g1.z, s1); s1 = fmaf(w.w, g1.w, s1);
            s2 = fmaf(w.x, g2.x, s2); s2 = fmaf(w.y, g2.y, s2);
            s2 = fmaf(w.z, g2.z, s2); s2 = fmaf(w.w, g2.w, s2);
        }
        const float cb = conv_b[c];
        float* shf = (float*)sh;                 // h[bsub][384]
        shf[bsub * 384 + 0 * NC + c] = s0 + cb * sSk[0] + fc3_b[0];
        shf[bsub * 384 + 1 * NC + c] = s1 + cb * sSk[1] + fc4_b[0];
        shf[bsub * 384 + 2 * NC + c] = s2 + cb * sSk[2] + fc5_b[0];
    }
    __syncthreads();   // all conv_w reads done; safe to overwrite W

    // Phase C1: stage fc_w (128 rows x 96 f4) padded to stride 97
    {
        const float4* fwg = (const float4*)fc_w;
        #pragma unroll
        for (int j = tid; j < NC * 96; j += 512) {
            const int r = j / 96, i = j % 96;
            W[r * 97 + i] = __ldg(&fwg[j]);
        }
    }
    __syncthreads();

    // Phase C2: private fc dots. thread -> (co = c, bsub)
    {
        float o = 0.f;
        #pragma unroll 8
        for (int i = 0; i < 96; i++) {
            const float4 w = W[c * 97 + i];      // stride 97: conflict-free
            const float4 h = sh[bsub * 96 + i];  // broadcast
            o = fmaf(w.x, h.x, o); o = fmaf(w.y, h.y, o);
            o = fmaf(w.z, h.z, o); o = fmaf(w.w, h.w, o);
        }
        out[(b0 + bsub) * NC + c] = o + fc_b[c];
    }
}

// ---------------------------------------------------------------------------
extern "C" void kernel_launch(void* const* d_in, const int* in_sizes, int n_in,
                              void* d_out, int out_size) {
    const int*   x       = (const int*)  d_in[0];
    const float* embed_w = (const float*)d_in[1];
    const float* conv_w  = (const float*)d_in[2];
    const float* conv_b  = (const float*)d_in[3];
    const float* fc3_w   = (const float*)d_in[4];
    const float* fc3_b   = (const float*)d_in[5];
    const float* fc4_w   = (const float*)d_in[6];
    const float* fc4_b   = (const float*)d_in[7];
    const float* fc5_w   = (const float*)d_in[8];
    const float* fc5_b   = (const float*)d_in[9];
    const float* fc_w    = (const float*)d_in[10];
    const float* fc_b    = (const float*)d_in[11];
    float* out = (float*)d_out;

    static int smem_set = 0;
    if (!smem_set) {
        cudaFuncSetAttribute(epilogue_kernel,
                             cudaFuncAttributeMaxDynamicSharedMemorySize, EPI_SMEM);
        smem_set = 1;
    }

    gather_kernel<<<NB * CH, 320>>>(x, embed_w, fc3_w, fc4_w, fc5_w);
    epilogue_kernel<<<16, 512, EPI_SMEM>>>(conv_w, conv_b, fc3_w, fc3_b,
                                           fc4_w, fc4_b, fc5_w, fc5_b,
                                           fc_w, fc_b, out);
}